// round 11
// baseline (speedup 1.0000x reference)
#include <cuda_runtime.h>
#include <math.h>

#define FRAME_SIZE 160
#define LPC_N 16
#define T_LEN 2400
#define T4 (T_LEN / 4)              // 600 float4 groups per row
#define N_FRAMES 15
#define B_SZ 1024

#define OGPW 60                     // output groups per warp (240 samples)
#define WARPS_PER_ROW (T4 / OGPW)   // 10
#define WPB 4                       // warps per block
#define NTHREADS (WPB * 32)
#define TOTAL_WARPS (B_SZ * WARPS_PER_ROW)   // 10240
#define NBLOCKS (TOTAL_WARPS / WPB)          // 2560

#define SCALE    (255.0f / 32768.0f)
#define SCALE_1  (32768.0f / 255.0f)

__device__ __forceinline__ float ex2_approx(float x) {
    float y; asm("ex2.approx.f32 %0, %1;" : "=f"(y) : "f"(x)); return y;
}
__device__ __forceinline__ float lg2_approx(float x) {
    float y; asm("lg2.approx.f32 %0, %1;" : "=f"(y) : "f"(x)); return y;
}

// mu-law (0..255) -> linear.  exp(u/128*ln256) == 2^(u/16).  u2l(128) == 0.
__device__ __forceinline__ float u2l(float v) {
    float u = v - 128.0f;
    float m = fmaf(SCALE_1, ex2_approx(fabsf(u) * 0.0625f), -SCALE_1);
    return copysignf(m, u);
}
// l2u(-a) = clip(128 - copysign(16*log2(1 + SCALE*|a|), a), 0, 255)
__device__ __forceinline__ float l2u_neg(float a) {
    float u = lg2_approx(fmaf(SCALE, fabsf(a), 1.0f));
    float s = copysignf(16.0f, a);
    return fminf(fmaxf(fmaf(-s, u, 128.0f), 0.0f), 255.0f);
}

__device__ __forceinline__ float4 dec4(float4 v) {
    float4 d;
    d.x = u2l(v.x); d.y = u2l(v.y); d.z = u2l(v.z); d.w = u2l(v.w);
    return d;
}

// Warp-autonomous, zero wasted passes:
//  - warp w: row b = w/10, segment r = w%10; owns output groups [60r, 60r+60)
//  - every lane decodes exactly 2 groups (64 groups incl. 4-group halo)
//  - lanes 0..29 each produce 2 output groups from one 24-sample window
//  - __syncwarp only; no block barrier
__global__ __launch_bounds__(NTHREADS)
void diff_pred_kernel(const float4* __restrict__ sig,
                      const float*  __restrict__ lpc,
                      float4* __restrict__ out) {
    __shared__ __align__(16) float4 sxw[WPB][OGPW + 4];   // 64 groups per warp

    const int wid = threadIdx.x >> 5;
    const int l   = threadIdx.x & 31;
    const int w   = blockIdx.x * WPB + wid;
    const int b   = w / WARPS_PER_ROW;
    const int r   = w - b * WARPS_PER_ROW;
    const int qs  = OGPW * r - 4;            // first decoded group (row-local)

    const float4* srow = sig + (size_t)b * T4;

    // ---- front-batch all global loads ----
    const int q0 = qs + 2 * l;               // this lane's two decode groups
    const float4 pad = make_float4(128.f, 128.f, 128.f, 128.f);  // decodes to 0
    float4 v0 = (q0 >= 0)     ? srow[q0]     : pad;
    float4 v1 = (q0 + 1 >= 0) ? srow[q0 + 1] : pad;

    // coefficients for this lane's output pair (same frame for both groups)
    float4 c0, c1, c2, c3;
    if (l < OGPW / 2) {
        const int G = OGPW * r + 2 * l;      // output group index in row
        const int f = G / (FRAME_SIZE / 4);  // frame = G/40
        const float4* lrow = (const float4*)(lpc + (size_t)b * (N_FRAMES * LPC_N)
                                             + f * LPC_N);
        c0 = lrow[0]; c1 = lrow[1]; c2 = lrow[2]; c3 = lrow[3];
    }

    // ---- decode both groups into this warp's strip ----
    sxw[wid][2 * l]     = dec4(v0);
    sxw[wid][2 * l + 1] = dec4(v1);
    __syncwarp();

    if (l >= OGPW / 2) return;

    // 24-sample window sxw[wid][2l .. 2l+5] covers both output groups
    float x[24];
#pragma unroll
    for (int k = 0; k < 6; ++k) {
        float4 xx = sxw[wid][2 * l + k];
        x[4 * k] = xx.x; x[4 * k + 1] = xx.y; x[4 * k + 2] = xx.z; x[4 * k + 3] = xx.w;
    }

    const float c[LPC_N] = { c0.x, c0.y, c0.z, c0.w, c1.x, c1.y, c1.z, c1.w,
                             c2.x, c2.y, c2.z, c2.w, c3.x, c3.y, c3.z, c3.w };

    // group A samples: x[16+j-i]; group B samples: x[20+j-i]
    float a0 = 0.f, a1 = 0.f, a2 = 0.f, a3 = 0.f;
    float a4 = 0.f, a5 = 0.f, a6 = 0.f, a7 = 0.f;
#pragma unroll
    for (int i = 0; i < LPC_N; ++i) {
        const float ci = c[i];
        a0 = fmaf(ci, x[16 - i], a0);
        a1 = fmaf(ci, x[17 - i], a1);
        a2 = fmaf(ci, x[18 - i], a2);
        a3 = fmaf(ci, x[19 - i], a3);
        a4 = fmaf(ci, x[20 - i], a4);
        a5 = fmaf(ci, x[21 - i], a5);
        a6 = fmaf(ci, x[22 - i], a6);
        a7 = fmaf(ci, x[23 - i], a7);
    }

    float4 rA, rB;
    rA.x = l2u_neg(a0); rA.y = l2u_neg(a1); rA.z = l2u_neg(a2); rA.w = l2u_neg(a3);
    rB.x = l2u_neg(a4); rB.y = l2u_neg(a5); rB.z = l2u_neg(a6); rB.w = l2u_neg(a7);

    float4* orow = out + (size_t)b * T4;
    const int og = OGPW * r + 2 * l;
    orow[og]     = rA;
    orow[og + 1] = rB;
}

extern "C" void kernel_launch(void* const* d_in, const int* in_sizes, int n_in,
                              void* d_out, int out_size) {
    const float4* sig = (const float4*)d_in[0];  // (B, 2400, 1) f32
    const float*  lpc = (const float*)d_in[1];   // (B, 15, 16) f32
    float4* out = (float4*)d_out;                // (B, 2400, 1) f32

    diff_pred_kernel<<<NBLOCKS, NTHREADS>>>(sig, lpc, out);
}